// round 1
// baseline (speedup 1.0000x reference)
#include <cuda_runtime.h>

#define HH 2048
#define WW 2048

// Scratch (device globals; no allocation allowed)
__device__ float4 g_part[4096];        // per-row partials: (m, s, sx, unused)
__device__ unsigned int g_cnt = 0;     // completion counter (self-resetting)
__device__ float g_state[3];           // dis, dis_sum, dis_num

__device__ __forceinline__ float neg_inf() { return __int_as_float(0xff800000); }

// logsumexp-style merge of (max, sum, sum_x, sum_y)
__device__ __forceinline__ void merge4(float &M, float &S, float &Sx, float &Sy,
                                       float m2, float s2, float sx2, float sy2) {
    float nm = fmaxf(M, m2);
    if (nm == neg_inf()) return;  // both empty
    float a = expf(M - nm);
    float b = expf(m2 - nm);
    S  = S  * a + s2  * b;
    Sx = Sx * a + sx2 * b;
    Sy = Sy * a + sy2 * b;
    M = nm;
}

// Block-wide merge reduce; result valid on thread 0.
__device__ void block_merge(float &M, float &S, float &Sx, float &Sy) {
    __shared__ float bm[8][4];
    int tid = threadIdx.x, lane = tid & 31, w = tid >> 5;
    #pragma unroll
    for (int o = 16; o; o >>= 1) {
        float m2 = __shfl_down_sync(0xffffffffu, M, o);
        float s2 = __shfl_down_sync(0xffffffffu, S, o);
        float x2 = __shfl_down_sync(0xffffffffu, Sx, o);
        float y2 = __shfl_down_sync(0xffffffffu, Sy, o);
        merge4(M, S, Sx, Sy, m2, s2, x2, y2);
    }
    __syncthreads();
    if (lane == 0) { bm[w][0] = M; bm[w][1] = S; bm[w][2] = Sx; bm[w][3] = Sy; }
    __syncthreads();
    if (tid == 0) {
        #pragma unroll
        for (int k = 1; k < 8; k++)
            merge4(M, S, Sx, Sy, bm[k][0], bm[k][1], bm[k][2], bm[k][3]);
    }
}

// One block reduces one 2048-float row: writes (rowmax, sum e, sum x*e) to g_part[slot].
// Values are pre-scaled by BETA=100.
__device__ void row_partial(const float * __restrict__ rowp, int slot) {
    __shared__ float sm_[8], ss_[8], sxx_[8];
    int tid = threadIdx.x;
    const float4 *p4 = reinterpret_cast<const float4*>(rowp);
    float4 A = p4[tid];
    float4 B = p4[tid + 256];
    float v[8] = {A.x, A.y, A.z, A.w, B.x, B.y, B.z, B.w};
    #pragma unroll
    for (int k = 0; k < 8; k++) v[k] *= 100.0f;
    float lm = v[0];
    #pragma unroll
    for (int k = 1; k < 8; k++) lm = fmaxf(lm, v[k]);
    #pragma unroll
    for (int o = 16; o; o >>= 1) lm = fmaxf(lm, __shfl_xor_sync(0xffffffffu, lm, o));
    if ((tid & 31) == 0) sm_[tid >> 5] = lm;
    __syncthreads();
    float m = sm_[0];
    #pragma unroll
    for (int k = 1; k < 8; k++) m = fmaxf(m, sm_[k]);

    float s = 0.f, sx = 0.f;
    float c0 = (float)(tid * 4);
    #pragma unroll
    for (int k = 0; k < 4; k++) { float e = expf(v[k] - m);     s += e; sx += (c0 + (float)k) * e; }
    #pragma unroll
    for (int k = 0; k < 4; k++) { float e = expf(v[4 + k] - m); s += e; sx += (1024.0f + c0 + (float)k) * e; }
    #pragma unroll
    for (int o = 16; o; o >>= 1) {
        s  += __shfl_xor_sync(0xffffffffu, s, o);
        sx += __shfl_xor_sync(0xffffffffu, sx, o);
    }
    if ((tid & 31) == 0) { ss_[tid >> 5] = s; sxx_[tid >> 5] = sx; }
    __syncthreads();
    if (tid == 0) {
        float S = 0.f, SX = 0.f;
        #pragma unroll
        for (int k = 0; k < 8; k++) { S += ss_[k]; SX += sxx_[k]; }
        g_part[slot] = make_float4(m, S, SX, 0.f);
    }
}

// ---------------- Kernel 1: full soft-argmax of channels 9 & 10 ----------------
__global__ void __launch_bounds__(256) full_kernel(const float * __restrict__ hm, float *out) {
    const int task = blockIdx.x;           // 0..4095
    const int ch   = 9 + (task >> 11);
    const int row  = task & (HH - 1);
    const float *rowp = hm + ((size_t)ch * HH + row) * WW;

    row_partial(rowp, task);

    __shared__ bool s_last;
    __threadfence();
    if (threadIdx.x == 0) {
        unsigned t = atomicAdd(&g_cnt, 1u);
        s_last = (t == gridDim.x - 1);
    }
    __syncthreads();
    if (!s_last) return;

    // finisher: combine per-row partials for each channel
    __shared__ float ay_s[2];
    int tid = threadIdx.x;
    for (int c = 0; c < 2; c++) {
        float M = neg_inf(), S = 0.f, Sx = 0.f, Sy = 0.f;
        for (int r = tid; r < HH; r += 256) {
            float4 p = g_part[c * HH + r];
            merge4(M, S, Sx, Sy, p.x, p.y, p.z, (float)r * p.y);
        }
        block_merge(M, S, Sx, Sy);
        if (tid == 0) {
            float ax = Sx / S, ay = Sy / S;
            out[(9 + c) * 2 + 0] = ax;
            out[(9 + c) * 2 + 1] = ay;
            ay_s[c] = ay;
        }
        __syncthreads();
    }
    if (tid == 0) {
        g_state[0] = ay_s[1] - ay_s[0];  // dis0 = y10 - y9
        g_state[1] = 0.f;                // dis_sum
        g_state[2] = 0.f;                // dis_num
        g_cnt = 0;
    }
}

// ---------------- Kernels 2..10: banded soft-argmax for channel i = 8..0 ----------------
__global__ void __launch_bounds__(256) band_kernel(const float * __restrict__ hm, float *out, int i) {
    // Every thread recomputes scalar band logic from global state (written by prev kernel).
    // __f*_rn intrinsics block FMA contraction to match the reference op-for-op.
    float dis = g_state[0], ds = g_state[1], dn = g_state[2];
    float y1 = out[(i + 1) * 2 + 1];
    float y2 = out[(i + 2) * 2 + 1];
    float last_y = floorf(y1);
    float tmp = ceilf(__fsub_rn(y2, y1));
    if (fabsf(__fsub_rn(tmp, dis)) > __fmul_rn(0.35f, dis)) {
        ds  = __fadd_rn(ds, tmp);
        dn  = __fadd_rn(dn, 1.0f);
        dis = __fdiv_rn(ds, fmaxf(dn, 1.0f));
    }
    float t  = __fmul_rn(1.8f, dis);
    float sr = __fsub_rn(last_y, t);
    float end_y   = rintf(__fadd_rn(sr, t));   // round-half-even, same as jnp.round
    float start_y = rintf(sr);

    int r0 = (start_y <= 0.f) ? 0  : (start_y >= (float)HH       ? HH      : (int)start_y);
    int r1 = (end_y   <  0.f) ? -1 : (end_y   >= (float)(HH - 1) ? HH - 1  : (int)end_y);

    const int row = blockIdx.x;
    const int tid = threadIdx.x;

    if (row >= r0 && row <= r1) {
        const float *rowp = hm + ((size_t)i * HH + row) * WW;
        row_partial(rowp, row);
    }

    __shared__ bool s_last;
    __threadfence();
    if (tid == 0) {
        unsigned tq = atomicAdd(&g_cnt, 1u);
        s_last = (tq == gridDim.x - 1);
    }
    __syncthreads();
    if (!s_last) return;

    // finisher: combine band rows + closed-form out-of-band contribution
    float M = neg_inf(), S = 0.f, Sx = 0.f, Sy = 0.f;
    if (r1 >= r0) {
        for (int r = r0 + tid; r <= r1; r += 256) {
            float4 p = g_part[r];
            merge4(M, S, Sx, Sy, p.x, p.y, p.z, (float)r * p.y);
        }
    }
    block_merge(M, S, Sx, Sy);

    if (tid == 0) {
        float Rn = (r1 >= r0) ? (float)(r1 - r0 + 1) : 0.f;
        float mb = M;
        float m;
        if (Rn >= (float)HH)      m = mb;                 // band covers everything
        else if (Rn > 0.f)        m = fmaxf(mb, 0.f);     // zeros exist outside band
        else                      m = 0.f;                // empty band: all-zero map
        float sc = (Rn > 0.f) ? expf(mb - m) : 0.f;
        S *= sc; Sx *= sc; Sy *= sc;

        if (Rn < (float)HH) {
            const float NTOT  = 4194304.f;      // H*W
            const float SXROW = 2096128.f;      // W*(W-1)/2
            const float SXTOT = 4292870144.f;   // H * SXROW
            const float SYTOT = 4292870144.f;   // W * H*(H-1)/2
            float e0   = expf(-m);
            float Nin  = Rn * 2048.f;
            float SxIn = Rn * SXROW;
            float SyIn = 2048.f * (0.5f * (float)(r0 + r1) * Rn);
            S  += (NTOT  - Nin ) * e0;
            Sx += (SXTOT - SxIn) * e0;
            Sy += (SYTOT - SyIn) * e0;
        }
        out[i * 2 + 0] = Sx / S;
        out[i * 2 + 1] = Sy / S;
        g_state[0] = dis; g_state[1] = ds; g_state[2] = dn;
        g_cnt = 0;
    }
}

extern "C" void kernel_launch(void* const* d_in, const int* in_sizes, int n_in,
                              void* d_out, int out_size) {
    const float *hm = (const float*)d_in[0];
    float *out = (float*)d_out;
    (void)in_sizes; (void)n_in; (void)out_size;

    full_kernel<<<4096, 256>>>(hm, out);
    for (int i = 8; i >= 0; i--)
        band_kernel<<<2048, 256>>>(hm, out, i);
}

// round 2
// speedup vs baseline: 1.0528x; 1.0528x over previous
#include <cuda_runtime.h>

#define HH 2048
#define WW 2048
#define NB 148
#define NT 256

// Scratch (device globals; no allocation allowed)
__device__ float4 g_bpart[4][NB];        // [2],[3]: phase0 ch9/ch10; [0],[1]: band double-buffer
__device__ unsigned int g_arrive = 0;    // monotone across replays
__device__ unsigned int g_release = 0;   // monotone across replays

__device__ __forceinline__ float neg_inf() { return __int_as_float(0xff800000); }

// logsumexp-style merge of (max, sum, sum_x, sum_y)
__device__ __forceinline__ void merge4(float &M, float &S, float &Sx, float &Sy,
                                       float m2, float s2, float sx2, float sy2) {
    float nm = fmaxf(M, m2);
    if (nm == neg_inf()) return;  // both empty
    float a = expf(M - nm);
    float b = expf(m2 - nm);
    S  = S  * a + s2  * b;
    Sx = Sx * a + sx2 * b;
    Sy = Sy * a + sy2 * b;
    M = nm;
}

// Block-wide merge reduce; result valid on thread 0.
__device__ void block_merge(float &M, float &S, float &Sx, float &Sy) {
    __shared__ float bm[8][4];
    int tid = threadIdx.x, lane = tid & 31, w = tid >> 5;
    #pragma unroll
    for (int o = 16; o; o >>= 1) {
        float m2 = __shfl_down_sync(0xffffffffu, M, o);
        float s2 = __shfl_down_sync(0xffffffffu, S, o);
        float x2 = __shfl_down_sync(0xffffffffu, Sx, o);
        float y2 = __shfl_down_sync(0xffffffffu, Sy, o);
        merge4(M, S, Sx, Sy, m2, s2, x2, y2);
    }
    __syncthreads();   // also guards bm reuse across consecutive calls
    if (lane == 0) { bm[w][0] = M; bm[w][1] = S; bm[w][2] = Sx; bm[w][3] = Sy; }
    __syncthreads();
    if (tid == 0) {
        #pragma unroll
        for (int k = 1; k < 8; k++)
            merge4(M, S, Sx, Sy, bm[k][0], bm[k][1], bm[k][2], bm[k][3]);
    }
}

// Online softmax accumulate with underflow skip (dropped terms < e^-88, ~1e-28 rel).
__device__ __forceinline__ void acc(float &M, float &S, float &Sx, float &Sy,
                                    float v, float x, float y) {
    if (v > M - 88.f) {
        if (v > M) {
            float r = expf(M - v);   // expf(-inf)=0 handles first element
            S  = S  * r + 1.f;
            Sx = Sx * r + x;
            Sy = Sy * r + y;
            M = v;
        } else {
            float e = expf(v - M);
            S += e; Sx += x * e; Sy += y * e;
        }
    }
}

// Grid barrier: monotone counters, no resets -> graph-replay safe.
// Invariant at every launch start: g_arrive == g_release * NB.
__device__ __forceinline__ void gsync(unsigned &epoch, unsigned base) {
    __threadfence();
    __syncthreads();
    if (threadIdx.x == 0) {
        epoch++;
        unsigned target = base + epoch;          // releases after this barrier
        unsigned t = atomicAdd(&g_arrive, 1u);
        if (t == target * NB - 1u) {
            __threadfence();
            atomicAdd(&g_release, 1u);
        } else {
            while (*((volatile unsigned*)&g_release) < target) { __nanosleep(32); }
        }
    }
    __syncthreads();
    __threadfence();
}

__global__ void __launch_bounds__(NT, 1)
sa_kernel(const float * __restrict__ hm, float * __restrict__ out) {
    const int b = blockIdx.x;
    const int tid = threadIdx.x;
    __shared__ unsigned s_base;
    __shared__ int s_r0, s_r1;
    __shared__ float s_ay;
    __shared__ float s_ay2[2];

    if (tid == 0) s_base = *((volatile unsigned*)&g_release);
    __syncthreads();
    const unsigned base = s_base;
    unsigned epoch = 0;

    // ---------------- Phase 0: full soft-argmax of channels 9 & 10 ----------------
    {
        int c  = (b < 74) ? 0 : 1;
        int bb = (b < 74) ? b : b - 74;
        const float4 *p4 = reinterpret_cast<const float4*>(hm + (size_t)(9 + c) * HH * WW);
        float M = neg_inf(), S = 0.f, Sx = 0.f, Sy = 0.f;
        const int total  = HH * (WW / 4);   // 1,048,576 float4
        const int stride = 74 * NT;         // 18,944
        int idx = bb * NT + tid;
        // main loop, 2x batched for MLP
        for (; idx + stride < total; idx += 2 * stride) {
            float4 A = p4[idx];
            float4 B = p4[idx + stride];
            {
                float y  = (float)(idx >> 9);
                float x0 = (float)((idx & 511) << 2);
                acc(M, S, Sx, Sy, A.x * 100.f, x0,       y);
                acc(M, S, Sx, Sy, A.y * 100.f, x0 + 1.f, y);
                acc(M, S, Sx, Sy, A.z * 100.f, x0 + 2.f, y);
                acc(M, S, Sx, Sy, A.w * 100.f, x0 + 3.f, y);
            }
            {
                int j = idx + stride;
                float y  = (float)(j >> 9);
                float x0 = (float)((j & 511) << 2);
                acc(M, S, Sx, Sy, B.x * 100.f, x0,       y);
                acc(M, S, Sx, Sy, B.y * 100.f, x0 + 1.f, y);
                acc(M, S, Sx, Sy, B.z * 100.f, x0 + 2.f, y);
                acc(M, S, Sx, Sy, B.w * 100.f, x0 + 3.f, y);
            }
        }
        for (; idx < total; idx += stride) {
            float4 A = p4[idx];
            float y  = (float)(idx >> 9);
            float x0 = (float)((idx & 511) << 2);
            acc(M, S, Sx, Sy, A.x * 100.f, x0,       y);
            acc(M, S, Sx, Sy, A.y * 100.f, x0 + 1.f, y);
            acc(M, S, Sx, Sy, A.z * 100.f, x0 + 2.f, y);
            acc(M, S, Sx, Sy, A.w * 100.f, x0 + 3.f, y);
        }
        block_merge(M, S, Sx, Sy);
        if (tid == 0) g_bpart[2 + c][bb] = make_float4(M, S, Sx, Sy);
    }
    gsync(epoch, base);

    // ---------- Phase 0 finisher: every block reduces redundantly (identical results) ----------
    float yA, yB;                    // y_{i+1}, y_{i+2}
    float dis, dsum = 0.f, dnum = 0.f;
    for (int c = 0; c < 2; c++) {
        float M = neg_inf(), S = 0.f, Sx = 0.f, Sy = 0.f;
        if (tid < 74) { float4 p = g_bpart[2 + c][tid]; M = p.x; S = p.y; Sx = p.z; Sy = p.w; }
        block_merge(M, S, Sx, Sy);
        if (tid == 0) {
            float ax = Sx / S, ay = Sy / S;
            s_ay2[c] = ay;
            if (b == 0) { out[(9 + c) * 2 + 0] = ax; out[(9 + c) * 2 + 1] = ay; }
        }
        __syncthreads();
    }
    yA = s_ay2[0];                   // y9
    yB = s_ay2[1];                   // y10
    dis = __fsub_rn(yB, yA);         // dis0

    // ---------------- Band phases i = 8 .. 0 (one grid barrier each) ----------------
    for (int i = 8; i >= 0; i--) {
        if (tid == 0) {
            // scalar band logic; __f*_rn blocks FMA contraction to match reference
            float y1 = yA, y2 = yB;
            float last_y = floorf(y1);
            float tmp = ceilf(__fsub_rn(y2, y1));
            if (fabsf(__fsub_rn(tmp, dis)) > __fmul_rn(0.35f, dis)) {
                dsum = __fadd_rn(dsum, tmp);
                dnum = __fadd_rn(dnum, 1.0f);
                dis  = __fdiv_rn(dsum, fmaxf(dnum, 1.0f));
            }
            float t  = __fmul_rn(1.8f, dis);
            float sr = __fsub_rn(last_y, t);
            float end_y   = rintf(__fadd_rn(sr, t));   // round-half-even = jnp.round
            float start_y = rintf(sr);
            s_r0 = (start_y <= 0.f) ? 0  : (start_y >= (float)HH       ? HH     : (int)start_y);
            s_r1 = (end_y   <  0.f) ? -1 : (end_y   >= (float)(HH - 1) ? HH - 1 : (int)end_y);
        }
        __syncthreads();
        const int r0 = s_r0, r1 = s_r1;

        float M = neg_inf(), S = 0.f, Sx = 0.f, Sy = 0.f;
        for (int row = r0 + b; row <= r1; row += NB) {
            const float4 *rp = reinterpret_cast<const float4*>(hm + ((size_t)i * HH + row) * WW);
            float4 A = rp[tid];
            float4 B = rp[tid + NT];
            float yv = (float)row;
            float x0 = (float)(tid << 2);
            acc(M, S, Sx, Sy, A.x * 100.f, x0,       yv);
            acc(M, S, Sx, Sy, A.y * 100.f, x0 + 1.f, yv);
            acc(M, S, Sx, Sy, A.z * 100.f, x0 + 2.f, yv);
            acc(M, S, Sx, Sy, A.w * 100.f, x0 + 3.f, yv);
            float x1 = x0 + 1024.f;
            acc(M, S, Sx, Sy, B.x * 100.f, x1,       yv);
            acc(M, S, Sx, Sy, B.y * 100.f, x1 + 1.f, yv);
            acc(M, S, Sx, Sy, B.z * 100.f, x1 + 2.f, yv);
            acc(M, S, Sx, Sy, B.w * 100.f, x1 + 3.f, yv);
        }
        const int bi = (8 - i) & 1;   // double-buffer by band parity
        block_merge(M, S, Sx, Sy);
        if (tid == 0) g_bpart[bi][b] = make_float4(M, S, Sx, Sy);
        gsync(epoch, base);

        // finisher (redundant in every block): band rows + closed-form out-of-band term
        M = neg_inf(); S = 0.f; Sx = 0.f; Sy = 0.f;
        if (tid < NB) { float4 p = g_bpart[bi][tid]; M = p.x; S = p.y; Sx = p.z; Sy = p.w; }
        block_merge(M, S, Sx, Sy);
        if (tid == 0) {
            float Rn = (r1 >= r0) ? (float)(r1 - r0 + 1) : 0.f;
            float mb = M;
            float m;
            if (Rn >= 2048.f)      m = mb;               // band covers everything
            else if (Rn > 0.f)     m = fmaxf(mb, 0.f);   // zeros exist outside band
            else                   m = 0.f;              // empty band: all-zero map
            float sc = (Rn > 0.f) ? expf(mb - m) : 0.f;
            S *= sc; Sx *= sc; Sy *= sc;

            if (Rn < 2048.f) {
                const float NTOT  = 4194304.f;      // H*W
                const float SXROW = 2096128.f;      // W*(W-1)/2
                const float SXTOT = 4292870144.f;   // H * SXROW
                const float SYTOT = 4292870144.f;   // W * H*(H-1)/2
                float e0 = expf(-m);
                S  += (NTOT  - Rn * 2048.f) * e0;
                Sx += (SXTOT - Rn * SXROW ) * e0;
                Sy += (SYTOT - 2048.f * (0.5f * (float)(r0 + r1) * Rn)) * e0;
            }
            float ax = Sx / S, ay = Sy / S;
            s_ay = ay;
            if (b == 0) { out[i * 2 + 0] = ax; out[i * 2 + 1] = ay; }
        }
        __syncthreads();
        yB = yA;
        yA = s_ay;
    }
}

extern "C" void kernel_launch(void* const* d_in, const int* in_sizes, int n_in,
                              void* d_out, int out_size) {
    const float *hm = (const float*)d_in[0];
    float *out = (float*)d_out;
    (void)in_sizes; (void)n_in; (void)out_size;

    sa_kernel<<<NB, NT>>>(hm, out);
}